// round 1
// baseline (speedup 1.0000x reference)
#include <cuda_runtime.h>

#define NPTS    4096
#define BATCH   8
#define NSAMP   32
#define R2      0.0625f

// Preprocessed points: (2x, 2y, 2z, -(x^2+y^2+z^2))
__device__ float4 xyz4g[BATCH * NPTS];

__global__ void lse_prep_kernel(const float* __restrict__ xyz) {
    int i = blockIdx.x * blockDim.x + threadIdx.x;
    if (i < BATCH * NPTS) {
        float x = xyz[3 * i + 0];
        float y = xyz[3 * i + 1];
        float z = xyz[3 * i + 2];
        float sq = fmaf(x, x, fmaf(y, y, z * z));
        xyz4g[i] = make_float4(2.0f * x, 2.0f * y, 2.0f * z, -sq);
    }
}

// One warp per query point. 512 threads = 16 points per CTA.
__global__ __launch_bounds__(512) void lse_main_kernel(
    const float* __restrict__ w1, const float* __restrict__ b1,
    const float* __restrict__ w2, const float* __restrict__ b2,
    float* __restrict__ out)
{
    __shared__ float w2t[32 * 65];   // transposed, padded stride 65 -> conflict free
    __shared__ int   nbr[16][NSAMP];

    const int tid = threadIdx.x;

    // Stage w2 transposed: w2t[i*65 + o] = w2[o*32 + i]
    for (int t = tid; t < 64 * 32; t += 512) {
        int o = t >> 5, i = t & 31;
        w2t[i * 65 + o] = w2[t];
    }
    __syncthreads();

    const int lane = tid & 31;
    const int w    = tid >> 5;
    const int blk  = blockIdx.x;
    const int b    = blk >> 8;                  // 256 CTAs per batch
    const int n    = ((blk & 255) << 4) + w;    // this warp's query point

    // Per-lane weights (lane = output channel; lane handles ch lane and lane+32 of layer 2)
    const float w1x = w1[3 * lane + 0];
    const float w1y = w1[3 * lane + 1];
    const float w1z = w1[3 * lane + 2];
    const float b1v = b1[lane];
    const float b20 = b2[lane];
    const float b21 = b2[lane + 32];

    float w2a[32], w2b[32];
    #pragma unroll
    for (int i = 0; i < 32; i++) {
        w2a[i] = w2t[i * 65 + lane];
        w2b[i] = w2t[i * 65 + lane + 32];
    }

    const float4* __restrict__ P = xyz4g + b * NPTS;
    const float4 qn = P[n];
    const float xn = 0.5f * qn.x;
    const float yn = 0.5f * qn.y;
    const float zn = 0.5f * qn.z;
    const float s  = -qn.w - R2;   // sq_n - R^2

    // ---- Phase 1: ball query scan. valid <=> 2*dot(x_m,x_n) - sq_m > sq_n - R^2
    unsigned cnt = 0;
    for (int base = 0; base < NPTS; base += 32) {
        float4 p = P[base + lane];
        float acc = fmaf(p.x, xn, fmaf(p.y, yn, fmaf(p.z, zn, p.w)));
        bool valid = acc > s;
        unsigned mask = __ballot_sync(0xffffffffu, valid);
        if (valid) {
            unsigned pos = cnt + (unsigned)__popc(mask & ((1u << lane) - 1u));
            if (pos < NSAMP) nbr[w][pos] = base + lane;
        }
        cnt += (unsigned)__popc(mask);
        if (cnt >= NSAMP) break;   // warp-uniform (cnt derived from ballot)
    }
    const unsigned k = cnt < NSAMP ? cnt : NSAMP;  // always >= 1 (self is valid)
    __syncwarp();

    // ---- Phase 2: MLP + max pool over the k neighbors (warp-uniform loop)
    float pooled0 = 0.0f, pooled1 = 0.0f;   // relu outputs >= 0, k >= 1 -> init 0 safe
    for (unsigned j = 0; j < k; j++) {
        int m = nbr[w][j];
        float4 p = P[m];                     // uniform address -> broadcast
        float rx = 0.5f * (p.x - qn.x);      // exact: fl(2a-2b)*0.5 == fl(a-b)
        float ry = 0.5f * (p.y - qn.y);
        float rz = 0.5f * (p.z - qn.z);
        float h = fmaf(w1x, rx, fmaf(w1y, ry, fmaf(w1z, rz, b1v)));
        h = fmaxf(h, 0.0f);                  // h1[lane]
        float a0 = b20, a1 = b21;
        #pragma unroll
        for (int i = 0; i < 32; i++) {
            float hi = __shfl_sync(0xffffffffu, h, i);
            a0 = fmaf(w2a[i], hi, a0);
            a1 = fmaf(w2b[i], hi, a1);
        }
        pooled0 = fmaxf(pooled0, fmaxf(a0, 0.0f));
        pooled1 = fmaxf(pooled1, fmaxf(a1, 0.0f));
    }

    // ---- Output: [B, N, 65] = [pooled(64), density]
    float* o = out + (size_t)(b * NPTS + n) * 65;
    o[lane]      = pooled0;
    o[lane + 32] = pooled1;
    if (lane == 0) o[64] = (float)k * (1.0f / 64.0f);
}

extern "C" void kernel_launch(void* const* d_in, const int* in_sizes, int n_in,
                              void* d_out, int out_size) {
    const float* xyz = (const float*)d_in[0];
    const float* w1  = (const float*)d_in[1];
    const float* b1  = (const float*)d_in[2];
    const float* w2  = (const float*)d_in[3];
    const float* b2  = (const float*)d_in[4];
    float* out = (float*)d_out;

    lse_prep_kernel<<<(BATCH * NPTS + 255) / 256, 256>>>(xyz);
    lse_main_kernel<<<BATCH * (NPTS / 16), 512>>>(w1, b1, w2, b2, out);
}

// round 2
// speedup vs baseline: 2.6880x; 2.6880x over previous
#include <cuda_runtime.h>

#define NPTS    4096
#define BATCH   8
#define NSAMP   32
#define R2      0.0625f
#define QPW     4      // query points per warp

// Preprocessed points: (2x, 2y, 2z, -(x^2+y^2+z^2))
__device__ float4 xyz4g[BATCH * NPTS];

__global__ void lse_prep_kernel(const float* __restrict__ xyz) {
    int i = blockIdx.x * blockDim.x + threadIdx.x;
    if (i < BATCH * NPTS) {
        float x = xyz[3 * i + 0];
        float y = xyz[3 * i + 1];
        float z = xyz[3 * i + 2];
        float sq = fmaf(x, x, fmaf(y, y, z * z));
        xyz4g[i] = make_float4(2.0f * x, 2.0f * y, 2.0f * z, -sq);
    }
}

// 512 threads = 16 warps; each warp owns 4 query points => 64 queries / CTA.
__global__ __launch_bounds__(512, 1) void lse_main_kernel(
    const float* __restrict__ w1, const float* __restrict__ b1,
    const float* __restrict__ w2, const float* __restrict__ b2,
    float* __restrict__ out)
{
    __shared__ float w2t[32 * 65];            // transposed w2, padded
    __shared__ int   nbr[16][QPW][NSAMP];     // 8KB neighbor lists

    const int tid = threadIdx.x;

    // Stage w2 transposed: w2t[i*65 + o] = w2[o*32 + i]
    for (int t = tid; t < 64 * 32; t += 512) {
        int o = t >> 5, i = t & 31;
        w2t[i * 65 + o] = w2[t];
    }
    __syncthreads();

    const int lane  = tid & 31;
    const int w     = tid >> 5;
    const int b     = blockIdx.x >> 6;                       // 64 CTAs per batch
    const int nbase = ((blockIdx.x & 63) << 6) + (w << 2);   // first of 4 queries

    const float4* __restrict__ P = xyz4g + b * NPTS;

    float xn[QPW], yn[QPW], zn[QPW], s[QPW];
    unsigned cnt[QPW];
    #pragma unroll
    for (int q = 0; q < QPW; q++) {
        float4 qn = P[nbase + q];
        xn[q] = 0.5f * qn.x;          // = x_n exactly
        yn[q] = 0.5f * qn.y;
        zn[q] = 0.5f * qn.z;
        s[q]  = -qn.w - R2;           // sq_n - R^2
        cnt[q] = 0;
    }

    // ---- Phase 1: ball-query scan, no early exit (enables pipelining).
    // valid <=> 2*dot(x_m,x_n) - sq_m > sq_n - R^2
    #pragma unroll 4
    for (int base = 0; base < NPTS; base += 32) {
        float4 p = P[base + lane];
        #pragma unroll
        for (int q = 0; q < QPW; q++) {
            float acc = fmaf(p.x, xn[q], fmaf(p.y, yn[q], fmaf(p.z, zn[q], p.w)));
            bool v = acc > s[q];
            unsigned m = __ballot_sync(0xffffffffu, v);
            if (v) {
                unsigned pos = cnt[q] + (unsigned)__popc(m & ((1u << lane) - 1u));
                if (pos < NSAMP) nbr[w][q][pos] = base + lane;
            }
            cnt[q] += (unsigned)__popc(m);
        }
    }
    __syncwarp();

    // ---- Per-lane MLP weights (loaded AFTER the scan to keep phase-1 lean)
    const float w1x = w1[3 * lane + 0];
    const float w1y = w1[3 * lane + 1];
    const float w1z = w1[3 * lane + 2];
    const float b1v = b1[lane];
    const float b20 = b2[lane];
    const float b21 = b2[lane + 32];

    float w2a[32], w2b[32];
    #pragma unroll
    for (int i = 0; i < 32; i++) {
        w2a[i] = w2t[i * 65 + lane];
        w2b[i] = w2t[i * 65 + lane + 32];
    }

    // ---- Phase 2: MLP + max pool, warp-uniform loops
    #pragma unroll
    for (int q = 0; q < QPW; q++) {
        const unsigned k = cnt[q] < NSAMP ? cnt[q] : NSAMP;  // >= 1 (self)
        const float qx = xn[q], qy = yn[q], qz = zn[q];
        float p0 = 0.0f, p1 = 0.0f;   // relu >= 0, k >= 1 -> init 0 safe
        for (unsigned j = 0; j < k; j++) {
            int m = nbr[w][q][j];
            float4 p = P[m];                       // uniform -> broadcast
            float rx = fmaf(0.5f, p.x, -qx);       // exact fl(x_m - x_n)
            float ry = fmaf(0.5f, p.y, -qy);
            float rz = fmaf(0.5f, p.z, -qz);
            float h = fmaf(w1x, rx, fmaf(w1y, ry, fmaf(w1z, rz, b1v)));
            h = fmaxf(h, 0.0f);                    // h1[lane]
            float a0 = b20, a1 = b21;
            #pragma unroll
            for (int i = 0; i < 32; i++) {
                float hi = __shfl_sync(0xffffffffu, h, i);
                a0 = fmaf(w2a[i], hi, a0);
                a1 = fmaf(w2b[i], hi, a1);
            }
            p0 = fmaxf(p0, fmaxf(a0, 0.0f));
            p1 = fmaxf(p1, fmaxf(a1, 0.0f));
        }
        float* o = out + (size_t)(b * NPTS + nbase + q) * 65;
        o[lane]      = p0;
        o[lane + 32] = p1;
        if (lane == 0) o[64] = (float)k * (1.0f / 64.0f);
    }
}

extern "C" void kernel_launch(void* const* d_in, const int* in_sizes, int n_in,
                              void* d_out, int out_size) {
    const float* xyz = (const float*)d_in[0];
    const float* w1  = (const float*)d_in[1];
    const float* b1  = (const float*)d_in[2];
    const float* w2  = (const float*)d_in[3];
    const float* b2  = (const float*)d_in[4];
    float* out = (float*)d_out;

    lse_prep_kernel<<<(BATCH * NPTS + 255) / 256, 256>>>(xyz);
    lse_main_kernel<<<BATCH * (NPTS / QPW / 16), 512>>>(w1, b1, w2, b2, out);
}